// round 14
// baseline (speedup 1.0000x reference)
#include <cuda_runtime.h>
#include <cuda_bf16.h>
#include <math.h>
#include <stdint.h>

#define BATCH   65536
#define DIN     118
#define NS      128
#define NOUTC   10
#define NEL     (BATCH*NS)
#define ROWS_PB 64
#define NTILES  (BATCH/ROWS_PB)
#define NBLOCKS 148
#define MAXIT   20
#define RTOLv   1e-3f
#define ATOLv   1e-3f

#define LDX     264
#define XH_OFF  0
#define XL_OFF  33792
#define HH_OFF  67584
#define HL_OFF  101376
#define WH_OFF  135168          // 2 async W buffer slots
#define SLOT    33792
#define SMEM_BYTES (135168 + 2*33792)

__device__ float g_ybuf[2][NEL];
__device__ float g_k[7][NEL];
__device__ __align__(16) __nv_bfloat16 g_w1h[128*264], g_w1l[128*264];
__device__ __align__(16) __nv_bfloat16 g_w2h[256*264], g_w2l[256*264];
__device__ __align__(16) __nv_bfloat16 g_w3h[256*136], g_w3l[256*136];

struct Ctrl {
    double sum0, sum1, sum2, errsum;
    float  t, dt, dt_last, last_t, h0, d1;
    int    done, cur, k0slot;
};
__device__ Ctrl g_ctrl;
#define VC ((volatile Ctrl*)&g_ctrl)

__device__ unsigned g_bar_count = 0;
__device__ volatile unsigned g_bar_phase = 0;
__device__ __forceinline__ void grid_barrier() {
    __syncthreads();
    if (threadIdx.x == 0) {
        unsigned ph = g_bar_phase;
        __threadfence();
        if (atomicAdd(&g_bar_count, 1u) == NBLOCKS - 1) {
            g_bar_count = 0; __threadfence(); g_bar_phase = ph + 1;
        } else { while (g_bar_phase == ph) { } }
        __threadfence();
    }
    __syncthreads();
}

__constant__ float c_beta[6][6] = {
    {(float)(1.0/5.0),0.f,0.f,0.f,0.f,0.f},
    {(float)(3.0/40.0),(float)(9.0/40.0),0.f,0.f,0.f,0.f},
    {(float)(44.0/45.0),(float)(-56.0/15.0),(float)(32.0/9.0),0.f,0.f,0.f},
    {(float)(19372.0/6561.0),(float)(-25360.0/2187.0),(float)(64448.0/6561.0),(float)(-212.0/729.0),0.f,0.f},
    {(float)(9017.0/3168.0),(float)(-355.0/33.0),(float)(46732.0/5247.0),(float)(49.0/176.0),(float)(-5103.0/18656.0),0.f},
    {(float)(35.0/384.0),0.f,(float)(500.0/1113.0),(float)(125.0/192.0),(float)(-2187.0/6784.0),(float)(11.0/84.0)}
};
__constant__ float c_errv[7] = {
    (float)(35.0/384.0 - 1951.0/21600.0), 0.f,
    (float)(500.0/1113.0 - 22642.0/50085.0),
    (float)(125.0/192.0 - 451.0/720.0),
    (float)(-2187.0/6784.0 + 12231.0/42400.0),
    (float)(11.0/84.0 - 649.0/6300.0),
    (float)(-1.0/60.0)
};
__constant__ float c_midv[7] = {
    (float)(6025192743.0/30085553152.0/2.0), 0.f,
    (float)(51252292925.0/65400821598.0/2.0),
    (float)(-2691868925.0/45128329728.0/2.0),
    (float)(187940372067.0/1594534317056.0/2.0),
    (float)(-1776094331.0/19743644256.0/2.0),
    (float)(11237099.0/235043384.0/2.0)
};

// ---- plain-target tensor / async helpers ----
__device__ __forceinline__ uint32_t smem_u32(const void* p) {
    uint32_t a;
    asm("{ .reg .u64 t; cvta.to.shared.u64 t, %1; cvt.u32.u64 %0, t; }" : "=r"(a) : "l"(p));
    return a;
}
__device__ __forceinline__ void ldsm_x4(uint32_t addr, uint32_t* a) {
    asm volatile("ldmatrix.sync.aligned.m8n8.x4.shared.b16 {%0,%1,%2,%3}, [%4];"
        : "=r"(a[0]), "=r"(a[1]), "=r"(a[2]), "=r"(a[3]) : "r"(addr));
}
__device__ __forceinline__ void ldsm_x4t(uint32_t addr, uint32_t* b) {
    asm volatile("ldmatrix.sync.aligned.m8n8.x4.trans.shared.b16 {%0,%1,%2,%3}, [%4];"
        : "=r"(b[0]), "=r"(b[1]), "=r"(b[2]), "=r"(b[3]) : "r"(addr));
}
__device__ __forceinline__ void mma16816(float* d, const uint32_t* a, const uint32_t* b) {
    asm volatile("mma.sync.aligned.m16n8k16.row.col.f32.bf16.bf16.f32 "
        "{%0,%1,%2,%3}, {%4,%5,%6,%7}, {%8,%9}, {%0,%1,%2,%3};"
        : "+f"(d[0]), "+f"(d[1]), "+f"(d[2]), "+f"(d[3])
        : "r"(a[0]), "r"(a[1]), "r"(a[2]), "r"(a[3]), "r"(b[0]), "r"(b[1]));
}
__device__ __forceinline__ void cp_async16(uint32_t saddr, const void* gptr) {
    asm volatile("cp.async.cg.shared.global [%0], [%1], 16;"
                 :: "r"(saddr), "l"(gptr));
}
#define CP_COMMIT() asm volatile("cp.async.commit_group;" ::: "memory")
#define CP_WAIT0()  asm volatile("cp.async.wait_group 0;" ::: "memory")

__device__ __forceinline__ uint32_t packsplit(float v0, float v1, uint32_t& lobits) {
    __nv_bfloat162 h = __floats2bfloat162_rn(v0, v1);
    __nv_bfloat162 l = __floats2bfloat162_rn(v0 - __bfloat162float(h.x),
                                             v1 - __bfloat162float(h.y));
    lobits = *(uint32_t*)&l;
    return *(uint32_t*)&h;
}

__device__ void build_img(__nv_bfloat16* dh, __nv_bfloat16* dl,
                          const float* __restrict__ W, int K, int N, int lddst,
                          int bid, int tid) {
    for (int i = bid*256 + tid; i < K*N; i += NBLOCKS*256) {
        int k = i / N, n = i - k*N;
        float x = W[(size_t)k*N + n];
        __nv_bfloat16 hb = __float2bfloat16(x);
        __nv_bfloat16 lb = __float2bfloat16(x - __bfloat162float(hb));
        dh[k*lddst + n] = hb;
        dl[k*lddst + n] = lb;
    }
}

__device__ __forceinline__ void stage_chunk(uint32_t sm32, int slot,
    const void* sh, const void* sl, int chb, int tid)
{
    uint32_t base = sm32 + WH_OFF + (uint32_t)slot*SLOT;
    const char* h = (const char*)sh;
    const char* l = (const char*)sl;
    for (int i = tid*16; i < chb; i += 256*16) {
        cp_async16(base + i,       h + i);
        cp_async16(base + chb + i, l + i);
    }
    CP_COMMIT();
}

// ---------------------------------------------------------------------------
// HMMA layer; continuous cp.async pipeline. Layer-3 (TOGLOBAL) epilogue can
// fuse the NEXT stage's input construction (ncf>0): v_next = y + sum cf*k,
// with the freshest k taken from registers (bit-identical to stored value).
// ---------------------------------------------------------------------------
template<int KD, int NOUT, int LDWE, bool RELU, bool TOGLOBAL>
__device__ __forceinline__ void mma_layer(
    char* smraw, uint32_t sm32,
    uint32_t xh_off, uint32_t xl_off,
    const __nv_bfloat16* __restrict__ gWh, const __nv_bfloat16* __restrict__ gWl,
    const float* __restrict__ bias,
    uint32_t hh_off, uint32_t hl_off,
    float* outG, int row0,
    bool do_err, float dt, int k0s,
    const float* __restrict__ y, const float* __restrict__ y1g,
    double& errloc,
    const __nv_bfloat16* nWh, const __nv_bfloat16* nWl, int nCHB,
    int& bufp,
    const float* cfn, int ncf, const float* const* kpp, float* y1out)
{
    constexpr int NT  = NOUT/16;
    constexpr int CHB = 32*LDWE*2;
    constexpr int NCH = KD/32;
    const int tid = threadIdx.x, w = tid >> 5, lane = tid & 31;
    const int r0  = (w & 3)*16;
    const int n0w = (w >> 2)*(NOUT/2);
    const int mrow = (lane & 7) + (lane & 8);
    const int mcol = (lane >> 4)*8;

    float d[NT][4];
    #pragma unroll
    for (int t = 0; t < NT; ++t) { d[t][0]=0.f; d[t][1]=0.f; d[t][2]=0.f; d[t][3]=0.f; }

    const uint32_t a_h = sm32 + xh_off + (uint32_t)((r0 + mrow)*LDX + mcol)*2;
    const uint32_t a_l = sm32 + xl_off + (uint32_t)((r0 + mrow)*LDX + mcol)*2;

    #pragma unroll 1
    for (int ch = 0; ch < NCH; ++ch) {
        if (ch + 1 < NCH)
            stage_chunk(sm32, (bufp + ch + 1) & 1,
                        gWh + (ch + 1)*32*LDWE, gWl + (ch + 1)*32*LDWE, CHB, tid);
        else if (nWh)
            stage_chunk(sm32, (bufp + ch + 1) & 1, nWh, nWl, nCHB, tid);

        const uint32_t bufo = WH_OFF + (uint32_t)((bufp + ch) & 1)*SLOT;
        const uint32_t wbH = sm32 + bufo + (uint32_t)(mrow*LDWE + mcol)*2;
        const uint32_t wbL = wbH + CHB;

        #pragma unroll
        for (int ks = 0; ks < 2; ++ks) {
            const int kg = ch*32 + ks*16;
            uint32_t ah[4], al[4];
            ldsm_x4(a_h + (uint32_t)kg*2, ah);
            ldsm_x4(a_l + (uint32_t)kg*2, al);
            #pragma unroll
            for (int tt = 0; tt < NT/2; ++tt) {
                uint32_t bh[4], bl[4];
                uint32_t boff = (uint32_t)(ks*16*LDWE + n0w + tt*16)*2;
                ldsm_x4t(wbH + boff, bh);
                ldsm_x4t(wbL + boff, bl);
                mma16816(d[2*tt],   ah, bh);
                mma16816(d[2*tt],   al, bh);
                mma16816(d[2*tt],   ah, bl);
                mma16816(d[2*tt+1], ah, bh+2);
                mma16816(d[2*tt+1], al, bh+2);
                mma16816(d[2*tt+1], ah, bl+2);
            }
        }
        CP_WAIT0();
        __syncthreads();
    }
    bufp = (bufp + NCH) & 1;

    if (!TOGLOBAL) {
        char* HHp = smraw + hh_off;
        char* HLp = smraw + hl_off;
        #pragma unroll
        for (int t = 0; t < NT; ++t) {
            int n = n0w + t*8 + (lane & 3)*2;
            float2 bb = *(const float2*)(bias + n);
            int r = r0 + (lane >> 2);
            float v0 = d[t][0] + bb.x, v1 = d[t][1] + bb.y;
            float v2 = d[t][2] + bb.x, v3 = d[t][3] + bb.y;
            if (RELU) {
                v0 = fmaxf(v0, 0.f); v1 = fmaxf(v1, 0.f);
                v2 = fmaxf(v2, 0.f); v3 = fmaxf(v3, 0.f);
            }
            uint32_t lob, hib;
            hib = packsplit(v0, v1, lob);
            *(uint32_t*)(HHp + (r*LDX + n)*2) = hib;
            *(uint32_t*)(HLp + (r*LDX + n)*2) = lob;
            hib = packsplit(v2, v3, lob);
            *(uint32_t*)(HHp + ((r+8)*LDX + n)*2) = hib;
            *(uint32_t*)(HLp + ((r+8)*LDX + n)*2) = lob;
        }
    } else {
        char* XHp = smraw + XH_OFF;
        char* XLp = smraw + XL_OFF;
        const float* kc0 = g_k[k0s];
        #pragma unroll
        for (int t = 0; t < NT; ++t) {
            int n = n0w + t*8 + (lane & 3)*2;
            float2 bb = *(const float2*)(bias + n);
            #pragma unroll
            for (int hf = 0; hf < 2; ++hf) {
                int r = r0 + (lane >> 2) + hf*8;
                float v0 = d[t][2*hf]   + bb.x;
                float v1 = d[t][2*hf+1] + bb.y;
                size_t gi = (size_t)(row0 + r)*NS + n;
                *(float2*)(outG + gi) = make_float2(v0, v1);
                if (do_err) {
                    float2 k0v = *(const float2*)(kc0 + gi);
                    float2 k2v = *(const float2*)(g_k[2] + gi);
                    float2 k3v = *(const float2*)(g_k[3] + gi);
                    float2 k4v = *(const float2*)(g_k[4] + gi);
                    float2 k5v = *(const float2*)(g_k[5] + gi);
                    float2 yv  = *(const float2*)(y + gi);
                    float2 y1v = *(const float2*)(y1g + gi);
                    float e0 = dt*(c_errv[0]*k0v.x + c_errv[2]*k2v.x + c_errv[3]*k3v.x
                                 + c_errv[4]*k4v.x + c_errv[5]*k5v.x + c_errv[6]*v0);
                    float t0 = ATOLv + RTOLv*fmaxf(fabsf(yv.x), fabsf(y1v.x));
                    float r0e = e0/t0; errloc += (double)r0e*r0e;
                    float e1 = dt*(c_errv[0]*k0v.y + c_errv[2]*k2v.y + c_errv[3]*k3v.y
                                 + c_errv[4]*k4v.y + c_errv[5]*k5v.y + c_errv[6]*v1);
                    float t1 = ATOLv + RTOLv*fmaxf(fabsf(yv.y), fabsf(y1v.y));
                    float r1e = e1/t1; errloc += (double)r1e*r1e;
                }
                if (ncf > 0) {
                    // next stage input: same fmaf order as phase-0; fresh k last
                    float2 yv = *(const float2*)(y + gi);
                    float a0 = yv.x, a1 = yv.y;
                    for (int j = 0; j < ncf - 1; ++j) {
                        float2 kv = *(const float2*)(kpp[j] + gi);
                        a0 = fmaf(cfn[j], kv.x, a0);
                        a1 = fmaf(cfn[j], kv.y, a1);
                    }
                    a0 = fmaf(cfn[ncf-1], v0, a0);
                    a1 = fmaf(cfn[ncf-1], v1, a1);
                    if (y1out) *(float2*)(y1out + gi) = make_float2(a0, a1);
                    uint32_t lob, hib = packsplit(a0, a1, lob);
                    *(uint32_t*)(XHp + (r*LDX + n)*2) = hib;
                    *(uint32_t*)(XLp + (r*LDX + n)*2) = lob;
                }
            }
        }
    }
    __syncthreads();
}

// ---------------------------------------------------------------------------
// Full stage for one 64-row tile. Phase-0 only for stages -1/-2/1; stages
// 2..6 consume X written by the previous stage's fused epilogue.
// ---------------------------------------------------------------------------
__device__ void tile_stage(
    int stage, int tile, int cur, int k0s, float dt, float h0,
    const float* __restrict__ b1, const float* __restrict__ b2,
    const float* __restrict__ b3,
    char* smraw, uint32_t sm32, double& errloc,
    int& bufp, bool& w1pre)
{
    const int tid  = threadIdx.x;
    const int row0 = tile * ROWS_PB;
    const float* y = g_ybuf[cur];
    float* ynext   = g_ybuf[cur ^ 1];
    const float* kp[6] = {g_k[k0s], g_k[1], g_k[2], g_k[3], g_k[4], g_k[5]};

    float coef[6];
    int nk, outslot;
    if (stage == -1)      { nk = 0; outslot = k0s; }
    else if (stage == -2) { nk = 1; coef[0] = h0; outslot = 1; }
    else {
        nk = stage;
        #pragma unroll
        for (int j = 0; j < 6; ++j) coef[j] = dt * c_beta[stage-1][j];
        outslot = (stage < 6) ? stage : (k0s ^ 6);
    }
    float* kout = g_k[outslot];

    // fused next-stage-input parameters (stages 1..5)
    float cfn[6];
    int ncf = 0;
    float* y1out = nullptr;
    if (stage >= 1 && stage <= 5) {
        ncf = stage + 1;
        #pragma unroll
        for (int j = 0; j < 6; ++j) cfn[j] = dt * c_beta[stage][j];
        if (stage == 5) y1out = ynext;
    }

    if (stage <= 1) {
        if (!w1pre)
            stage_chunk(sm32, bufp, g_w1h, g_w1l, 32*264*2, tid);
        // phase 0: build stage input, split to X
        char* XHp = smraw + XH_OFF;
        char* XLp = smraw + XL_OFF;
        for (int i = tid; i < ROWS_PB*NS/4; i += 256) {
            int r = i >> 5, c4 = i & 31, c = c4*4;
            size_t g4 = ((size_t)(row0 + r)*NS >> 2) + c4;
            float4 v = ((const float4*)y)[g4];
            for (int j = 0; j < nk; ++j) {
                float4 kv = ((const float4*)kp[j])[g4];
                v.x = fmaf(coef[j], kv.x, v.x);
                v.y = fmaf(coef[j], kv.y, v.y);
                v.z = fmaf(coef[j], kv.z, v.z);
                v.w = fmaf(coef[j], kv.w, v.w);
            }
            uint32_t off = (uint32_t)(r*LDX + c)*2;
            uint32_t lob, hib;
            hib = packsplit(v.x, v.y, lob);
            *(uint32_t*)(XHp + off) = hib;
            *(uint32_t*)(XLp + off) = lob;
            hib = packsplit(v.z, v.w, lob);
            *(uint32_t*)(XHp + off + 4) = hib;
            *(uint32_t*)(XLp + off + 4) = lob;
        }
        if (!w1pre) { CP_WAIT0(); w1pre = true; }
        __syncthreads();
    }

    double dz = 0.0;
    mma_layer<128,256,264,true ,false>(smraw, sm32, XH_OFF, XL_OFF,
        g_w1h, g_w1l, b1, HH_OFF, HL_OFF, nullptr, 0,
        false, 0.f, 0, nullptr, nullptr, dz,
        g_w2h, g_w2l, 32*264*2, bufp, nullptr, 0, nullptr, nullptr);
    mma_layer<256,256,264,true ,false>(smraw, sm32, HH_OFF, HL_OFF,
        g_w2h, g_w2l, b2, XH_OFF, XL_OFF, nullptr, 0,
        false, 0.f, 0, nullptr, nullptr, dz,
        g_w3h, g_w3l, 32*136*2, bufp, nullptr, 0, nullptr, nullptr);
    mma_layer<256,128,136,false,true >(smraw, sm32, XH_OFF, XL_OFF,
        g_w3h, g_w3l, b3, 0, 0, kout, row0,
        stage == 6, dt, k0s, y, ynext, errloc,
        g_w1h, g_w1l, 32*264*2, bufp, cfn, ncf, kp, y1out);
}

// ---------------------------------------------------------------------------
// Reductions / controller (frozen)
// ---------------------------------------------------------------------------
__device__ double block_reduce_d(double v, double* sh) {
    const int tid = threadIdx.x;
    sh[tid] = v;
    __syncthreads();
    #pragma unroll
    for (int s = 128; s > 0; s >>= 1) {
        if (tid < s) sh[tid] += sh[tid + s];
        __syncthreads();
    }
    double r = sh[0];
    __syncthreads();
    return r;
}
__device__ void ctrl_init_dev() {
    VC->sum0 = 0.0; VC->sum1 = 0.0; VC->sum2 = 0.0; VC->errsum = 0.0;
    VC->t = 0.f; VC->dt = 0.f; VC->dt_last = 0.f; VC->last_t = 0.f;
    VC->h0 = 0.f; VC->d1 = 0.f;
    VC->done = 0; VC->cur = 0; VC->k0slot = 0;
}
__device__ void ctrl_h0_dev() {
    float d0 = (float)sqrt(VC->sum0);
    float d1 = (float)sqrt(VC->sum1);
    float h0 = (d0 < 1e-5f || d1 < 1e-5f) ? 1e-6f : 0.01f * d0 / d1;
    VC->h0 = h0; VC->d1 = d1;
}
__device__ void ctrl_dt0_dev() {
    float h0 = VC->h0, d1 = VC->d1;
    float d2 = (float)sqrt(VC->sum2) / h0;
    float h1;
    if (d1 <= 1e-15f && d2 <= 1e-15f) h1 = fmaxf(1e-6f, h0 * 1e-3f);
    else h1 = powf(0.01f / fmaxf(d1, d2), 0.2f);
    VC->dt = fminf(100.f * h0, h1);
    VC->t = 0.f; VC->last_t = 0.f; VC->errsum = 0.0;
}
__device__ void ctrl_update_dev() {
    float err = (float)sqrt(VC->errsum / (double)NEL);
    float dfac = (err < 1.f) ? 1.f : 0.2f;
    float factor = fminf(10.f, fmaxf(powf(err, -0.2f) * 0.9f, dfac));
    float dtcur = VC->dt;
    float dtnew = (err == 0.f) ? dtcur * 10.f : dtcur * factor;
    dtnew = fmaxf(dtnew, 0.f);
    if (err <= 1.f) {
        VC->last_t = VC->t;
        VC->t      = VC->t + dtcur;
        VC->dt_last = dtcur;
        VC->cur    = VC->cur ^ 1;
        VC->k0slot = VC->k0slot ^ 6;
        if (VC->t >= 1.0f) VC->done = 1;
    }
    VC->dt = dtnew;
    VC->errsum = 0.0;
}

// ---------------------------------------------------------------------------
// Persistent kernel
// ---------------------------------------------------------------------------
__global__ void __launch_bounds__(256, 1)
ode_persistent(const float* __restrict__ x,
               const float* __restrict__ W1, const float* __restrict__ b1,
               const float* __restrict__ W2, const float* __restrict__ b2,
               const float* __restrict__ W3, const float* __restrict__ b3)
{
    extern __shared__ char smraw[];
    uint32_t sm32 = smem_u32(smraw);
    double* shred = (double*)smraw;
    const int tid = threadIdx.x, bid = blockIdx.x;
    int bufp = 0;
    bool w1pre = false;

    if (bid == 0 && tid == 0) ctrl_init_dev();

    build_img(g_w1h, g_w1l, W1, 128, 256, 264, bid, tid);
    build_img(g_w2h, g_w2l, W2, 256, 256, 264, bid, tid);
    build_img(g_w3h, g_w3l, W3, 256, 128, 136, bid, tid);

    for (int tile = bid; tile < NTILES; tile += NBLOCKS)
        for (int i = tid; i < ROWS_PB*NS; i += 256) {
            int r = i >> 7, cc = i & 127;
            size_t row = (size_t)tile*ROWS_PB + r;
            g_ybuf[0][row*NS + cc] = (cc < DIN) ? x[row*DIN + cc] : 0.f;
        }
    grid_barrier();

    // f0 -> slot 0
    double dummy = 0.0;
    for (int tile = bid; tile < NTILES; tile += NBLOCKS)
        tile_stage(-1, tile, 0, 0, 0.f, 0.f, b1, b2, b3, smraw, sm32, dummy,
                   bufp, w1pre);
    // d0/d1 norms
    {
        double s0 = 0.0, s1 = 0.0;
        const float4* y4 = (const float4*)g_ybuf[0];
        const float4* f4 = (const float4*)g_k[0];
        for (int tile = bid; tile < NTILES; tile += NBLOCKS) {
            size_t b4 = (size_t)tile*ROWS_PB*NS/4;
            for (int i = tid; i < ROWS_PB*NS/4; i += 256) {
                float4 y0 = y4[b4 + i], f0 = f4[b4 + i];
                float sc, a, b;
                sc = ATOLv + RTOLv*fabsf(y0.x); a = y0.x/sc; b = f0.x/sc; s0 += (double)a*a; s1 += (double)b*b;
                sc = ATOLv + RTOLv*fabsf(y0.y); a = y0.y/sc; b = f0.y/sc; s0 += (double)a*a; s1 += (double)b*b;
                sc = ATOLv + RTOLv*fabsf(y0.z); a = y0.z/sc; b = f0.z/sc; s0 += (double)a*a; s1 += (double)b*b;
                sc = ATOLv + RTOLv*fabsf(y0.w); a = y0.w/sc; b = f0.w/sc; s0 += (double)a*a; s1 += (double)b*b;
            }
        }
        double r0 = block_reduce_d(s0, shred);
        double r1 = block_reduce_d(s1, shred);
        if (tid == 0) { atomicAdd(&g_ctrl.sum0, r0); atomicAdd(&g_ctrl.sum1, r1); }
    }
    grid_barrier();
    if (bid == 0 && tid == 0) ctrl_h0_dev();
    grid_barrier();

    // probe -> slot 1
    {
        float h0v = VC->h0;
        for (int tile = bid; tile < NTILES; tile += NBLOCKS)
            tile_stage(-2, tile, 0, 0, 0.f, h0v, b1, b2, b3, smraw, sm32, dummy,
                       bufp, w1pre);
        double s2 = 0.0;
        const float4* y4 = (const float4*)g_ybuf[0];
        const float4* k04 = (const float4*)g_k[0];
        const float4* k14 = (const float4*)g_k[1];
        for (int tile = bid; tile < NTILES; tile += NBLOCKS) {
            size_t b4 = (size_t)tile*ROWS_PB*NS/4;
            for (int i = tid; i < ROWS_PB*NS/4; i += 256) {
                float4 y0 = y4[b4 + i], k0 = k04[b4 + i], k1 = k14[b4 + i];
                float sc, d;
                sc = ATOLv + RTOLv*fabsf(y0.x); d = (k1.x - k0.x)/sc; s2 += (double)d*d;
                sc = ATOLv + RTOLv*fabsf(y0.y); d = (k1.y - k0.y)/sc; s2 += (double)d*d;
                sc = ATOLv + RTOLv*fabsf(y0.z); d = (k1.z - k0.z)/sc; s2 += (double)d*d;
                sc = ATOLv + RTOLv*fabsf(y0.w); d = (k1.w - k0.w)/sc; s2 += (double)d*d;
            }
        }
        double r2 = block_reduce_d(s2, shred);
        if (tid == 0) atomicAdd(&g_ctrl.sum2, r2);
    }
    grid_barrier();
    if (bid == 0 && tid == 0) ctrl_dt0_dev();
    grid_barrier();

    // adaptive dopri5 attempts
    for (int it = 0; it < MAXIT; ++it) {
        if (VC->done) break;
        float dt = VC->dt;
        int cur = VC->cur, k0s = VC->k0slot;
        double eloc = 0.0;
        for (int tile = bid; tile < NTILES; tile += NBLOCKS)
            #pragma unroll 1
            for (int s = 1; s <= 6; ++s)
                tile_stage(s, tile, cur, k0s, dt, 0.f, b1, b2, b3,
                           smraw, sm32, eloc, bufp, w1pre);
        double rsum = block_reduce_d(eloc, shred);
        if (tid == 0) atomicAdd(&g_ctrl.errsum, rsum);
        grid_barrier();
        if (bid == 0 && tid == 0) ctrl_update_dev();
        grid_barrier();
    }
}

// ---------------------------------------------------------------------------
// Final: 4th-order interpolation at t=1, then linear layer @ Wl + bl
// ---------------------------------------------------------------------------
__global__ void __launch_bounds__(256)
final_kernel(const float* __restrict__ Wl, const float* __restrict__ bl,
             float* __restrict__ out)
{
    __shared__ float yt_s[64*132];
    __shared__ float wl_s[128*NOUTC];
    __shared__ float bl_s[NOUTC];
    const int tid = threadIdx.x;
    const int row0 = blockIdx.x * 64;

    for (int i = tid; i < 128*NOUTC; i += 256) wl_s[i] = Wl[i];
    if (tid < NOUTC) bl_s[tid] = bl[tid];

    const int cur = g_ctrl.cur;
    const int k0s = g_ctrl.k0slot;
    const float dtl = g_ctrl.dt_last;
    const float s  = (1.0f - g_ctrl.last_t) / (g_ctrl.t - g_ctrl.last_t);
    const float* yprev = g_ybuf[cur ^ 1];
    const float* ycur  = g_ybuf[cur];
    const float* k0p = g_k[k0s ^ 6];
    const float* k6p = g_k[k0s];

    for (int i = tid; i < 64*NS; i += 256) {
        int r = i >> 7, cc = i & 127;
        size_t g = (size_t)(row0 + r)*NS + cc;
        float y0e = yprev[g], y1e = ycur[g];
        float k0v = k0p[g], k6v = k6p[g];
        float kmid = c_midv[0]*k0v + c_midv[2]*g_k[2][g] + c_midv[3]*g_k[3][g]
                   + c_midv[4]*g_k[4][g] + c_midv[5]*g_k[5][g] + c_midv[6]*k6v;
        float ymid = y0e + dtl * kmid;
        float dy0 = dtl * k0v, dy1 = dtl * k6v;
        float a = -2.f*dy0 + 2.f*dy1 -  8.f*y0e -  8.f*y1e + 16.f*ymid;
        float b =  5.f*dy0 - 3.f*dy1 + 18.f*y0e + 14.f*y1e - 32.f*ymid;
        float c = -4.f*dy0 +     dy1 - 11.f*y0e -  5.f*y1e + 16.f*ymid;
        float d = dy0, e = y0e;
        yt_s[r*132 + cc] = (((a*s + b)*s + c)*s + d)*s + e;
    }
    __syncthreads();

    for (int idx = tid; idx < 64*NOUTC; idx += 256) {
        int r = idx / NOUTC, c = idx % NOUTC;
        float acc = bl_s[c];
        const float* yr = yt_s + r*132;
        #pragma unroll 8
        for (int kk = 0; kk < NS; ++kk)
            acc = fmaf(yr[kk], wl_s[kk*NOUTC + c], acc);
        out[(size_t)(row0 + r)*NOUTC + c] = acc;
    }
}

extern "C" void kernel_launch(void* const* d_in, const int* in_sizes, int n_in,
                              void* d_out, int out_size)
{
    const float* x  = (const float*)d_in[0];
    const float* W1 = (const float*)d_in[1];
    const float* b1 = (const float*)d_in[2];
    const float* W2 = (const float*)d_in[3];
    const float* b2 = (const float*)d_in[4];
    const float* W3 = (const float*)d_in[5];
    const float* b3 = (const float*)d_in[6];
    const float* Wl = (const float*)d_in[7];
    const float* bl = (const float*)d_in[8];
    float* out = (float*)d_out;

    cudaFuncSetAttribute(ode_persistent,
                         cudaFuncAttributeMaxDynamicSharedMemorySize, SMEM_BYTES);
    ode_persistent<<<NBLOCKS, 256, SMEM_BYTES>>>(x, W1, b1, W2, b2, W3, b3);
    final_kernel<<<NTILES, 256>>>(Wl, bl, out);
}

// round 15
// speedup vs baseline: 1.1480x; 1.1480x over previous
#include <cuda_runtime.h>
#include <cuda_bf16.h>
#include <math.h>
#include <stdint.h>

#define BATCH   65536
#define DIN     118
#define NS      128
#define NOUTC   10
#define NEL     (BATCH*NS)
#define ROWS_PB 64
#define NTILES  (BATCH/ROWS_PB)
#define NBLOCKS 148
#define MAXIT   20
#define RTOLv   1e-3f
#define ATOLv   1e-3f

#define LDX     264
#define XH_OFF  0
#define XL_OFF  33792
#define HH_OFF  67584
#define HL_OFF  101376
#define WH_OFF  135168          // 2 async W buffer slots
#define SLOT    34816           // max(2*CHB) = 2*64*136*2 for layer 3
#define SMEM_BYTES (135168 + 2*34816)

__device__ float g_ybuf[2][NEL];
__device__ float g_k[7][NEL];
__device__ __align__(16) __nv_bfloat16 g_w1h[128*264], g_w1l[128*264];
__device__ __align__(16) __nv_bfloat16 g_w2h[256*264], g_w2l[256*264];
__device__ __align__(16) __nv_bfloat16 g_w3h[256*136], g_w3l[256*136];

struct Ctrl {
    double sum0, sum1, sum2, errsum;
    float  t, dt, dt_last, last_t, h0, d1;
    int    done, cur, k0slot;
};
__device__ Ctrl g_ctrl;
#define VC ((volatile Ctrl*)&g_ctrl)

__device__ unsigned g_bar_count = 0;
__device__ volatile unsigned g_bar_phase = 0;
__device__ __forceinline__ void grid_barrier() {
    __syncthreads();
    if (threadIdx.x == 0) {
        unsigned ph = g_bar_phase;
        __threadfence();
        if (atomicAdd(&g_bar_count, 1u) == NBLOCKS - 1) {
            g_bar_count = 0; __threadfence(); g_bar_phase = ph + 1;
        } else { while (g_bar_phase == ph) { } }
        __threadfence();
    }
    __syncthreads();
}

__constant__ float c_beta[6][6] = {
    {(float)(1.0/5.0),0.f,0.f,0.f,0.f,0.f},
    {(float)(3.0/40.0),(float)(9.0/40.0),0.f,0.f,0.f,0.f},
    {(float)(44.0/45.0),(float)(-56.0/15.0),(float)(32.0/9.0),0.f,0.f,0.f},
    {(float)(19372.0/6561.0),(float)(-25360.0/2187.0),(float)(64448.0/6561.0),(float)(-212.0/729.0),0.f,0.f},
    {(float)(9017.0/3168.0),(float)(-355.0/33.0),(float)(46732.0/5247.0),(float)(49.0/176.0),(float)(-5103.0/18656.0),0.f},
    {(float)(35.0/384.0),0.f,(float)(500.0/1113.0),(float)(125.0/192.0),(float)(-2187.0/6784.0),(float)(11.0/84.0)}
};
__constant__ float c_errv[7] = {
    (float)(35.0/384.0 - 1951.0/21600.0), 0.f,
    (float)(500.0/1113.0 - 22642.0/50085.0),
    (float)(125.0/192.0 - 451.0/720.0),
    (float)(-2187.0/6784.0 + 12231.0/42400.0),
    (float)(11.0/84.0 - 649.0/6300.0),
    (float)(-1.0/60.0)
};
__constant__ float c_midv[7] = {
    (float)(6025192743.0/30085553152.0/2.0), 0.f,
    (float)(51252292925.0/65400821598.0/2.0),
    (float)(-2691868925.0/45128329728.0/2.0),
    (float)(187940372067.0/1594534317056.0/2.0),
    (float)(-1776094331.0/19743644256.0/2.0),
    (float)(11237099.0/235043384.0/2.0)
};

// ---- plain-target tensor / async helpers ----
__device__ __forceinline__ uint32_t smem_u32(const void* p) {
    uint32_t a;
    asm("{ .reg .u64 t; cvta.to.shared.u64 t, %1; cvt.u32.u64 %0, t; }" : "=r"(a) : "l"(p));
    return a;
}
__device__ __forceinline__ void ldsm_x4(uint32_t addr, uint32_t* a) {
    asm volatile("ldmatrix.sync.aligned.m8n8.x4.shared.b16 {%0,%1,%2,%3}, [%4];"
        : "=r"(a[0]), "=r"(a[1]), "=r"(a[2]), "=r"(a[3]) : "r"(addr));
}
__device__ __forceinline__ void ldsm_x4t(uint32_t addr, uint32_t* b) {
    asm volatile("ldmatrix.sync.aligned.m8n8.x4.trans.shared.b16 {%0,%1,%2,%3}, [%4];"
        : "=r"(b[0]), "=r"(b[1]), "=r"(b[2]), "=r"(b[3]) : "r"(addr));
}
__device__ __forceinline__ void mma16816(float* d, const uint32_t* a, const uint32_t* b) {
    asm volatile("mma.sync.aligned.m16n8k16.row.col.f32.bf16.bf16.f32 "
        "{%0,%1,%2,%3}, {%4,%5,%6,%7}, {%8,%9}, {%0,%1,%2,%3};"
        : "+f"(d[0]), "+f"(d[1]), "+f"(d[2]), "+f"(d[3])
        : "r"(a[0]), "r"(a[1]), "r"(a[2]), "r"(a[3]), "r"(b[0]), "r"(b[1]));
}
__device__ __forceinline__ void cp_async16(uint32_t saddr, const void* gptr) {
    asm volatile("cp.async.cg.shared.global [%0], [%1], 16;"
                 :: "r"(saddr), "l"(gptr));
}
#define CP_COMMIT() asm volatile("cp.async.commit_group;" ::: "memory")
#define CP_WAIT0()  asm volatile("cp.async.wait_group 0;" ::: "memory")

__device__ __forceinline__ uint32_t packsplit(float v0, float v1, uint32_t& lobits) {
    __nv_bfloat162 h = __floats2bfloat162_rn(v0, v1);
    __nv_bfloat162 l = __floats2bfloat162_rn(v0 - __bfloat162float(h.x),
                                             v1 - __bfloat162float(h.y));
    lobits = *(uint32_t*)&l;
    return *(uint32_t*)&h;
}

__device__ void build_img(__nv_bfloat16* dh, __nv_bfloat16* dl,
                          const float* __restrict__ W, int K, int N, int lddst,
                          int bid, int tid) {
    for (int i = bid*256 + tid; i < K*N; i += NBLOCKS*256) {
        int k = i / N, n = i - k*N;
        float x = W[(size_t)k*N + n];
        __nv_bfloat16 hb = __float2bfloat16(x);
        __nv_bfloat16 lb = __float2bfloat16(x - __bfloat162float(hb));
        dh[k*lddst + n] = hb;
        dl[k*lddst + n] = lb;
    }
}

// async-stage one W chunk (hi+lo) into buffer slot; commits a group
__device__ __forceinline__ void stage_chunk(uint32_t sm32, int slot,
    const void* sh, const void* sl, int chb, int tid)
{
    uint32_t base = sm32 + WH_OFF + (uint32_t)slot*SLOT;
    const char* h = (const char*)sh;
    const char* l = (const char*)sl;
    for (int i = tid*16; i < chb; i += 256*16) {
        cp_async16(base + i,       h + i);
        cp_async16(base + chb + i, l + i);
    }
    CP_COMMIT();
}

// ---------------------------------------------------------------------------
// HMMA layer; continuous cp.async pipeline; KCHR = staging chunk height.
// ---------------------------------------------------------------------------
template<int KD, int NOUT, int LDWE, int KCHR, bool RELU, bool TOGLOBAL>
__device__ __forceinline__ void mma_layer(
    char* smraw, uint32_t sm32,
    uint32_t xh_off, uint32_t xl_off,
    const __nv_bfloat16* __restrict__ gWh, const __nv_bfloat16* __restrict__ gWl,
    const float* __restrict__ bias,
    uint32_t hh_off, uint32_t hl_off,
    float* outG, int row0,
    bool do_err, float dt, int k0s,
    const float* __restrict__ y, const float* __restrict__ y1g,
    double& errloc,
    const __nv_bfloat16* nWh, const __nv_bfloat16* nWl, int nCHB,
    int& bufp)
{
    constexpr int NT  = NOUT/16;
    constexpr int CHB = KCHR*LDWE*2;
    constexpr int NCH = KD/KCHR;
    constexpr int NKS = KCHR/16;
    const int tid = threadIdx.x, w = tid >> 5, lane = tid & 31;
    const int r0  = (w & 3)*16;
    const int n0w = (w >> 2)*(NOUT/2);
    const int mrow = (lane & 7) + (lane & 8);
    const int mcol = (lane >> 4)*8;

    float d[NT][4];
    #pragma unroll
    for (int t = 0; t < NT; ++t) { d[t][0]=0.f; d[t][1]=0.f; d[t][2]=0.f; d[t][3]=0.f; }

    const uint32_t a_h = sm32 + xh_off + (uint32_t)((r0 + mrow)*LDX + mcol)*2;
    const uint32_t a_l = sm32 + xl_off + (uint32_t)((r0 + mrow)*LDX + mcol)*2;

    #pragma unroll 1
    for (int ch = 0; ch < NCH; ++ch) {
        if (ch + 1 < NCH)
            stage_chunk(sm32, (bufp + ch + 1) & 1,
                        gWh + (ch + 1)*KCHR*LDWE, gWl + (ch + 1)*KCHR*LDWE, CHB, tid);
        else if (nWh)
            stage_chunk(sm32, (bufp + ch + 1) & 1, nWh, nWl, nCHB, tid);

        const uint32_t bufo = WH_OFF + (uint32_t)((bufp + ch) & 1)*SLOT;
        const uint32_t wbH = sm32 + bufo + (uint32_t)(mrow*LDWE + mcol)*2;
        const uint32_t wbL = wbH + CHB;

        #pragma unroll
        for (int ks = 0; ks < NKS; ++ks) {
            const int kg = ch*KCHR + ks*16;
            uint32_t ah[4], al[4];
            ldsm_x4(a_h + (uint32_t)kg*2, ah);
            ldsm_x4(a_l + (uint32_t)kg*2, al);
            #pragma unroll
            for (int tt = 0; tt < NT/2; ++tt) {
                uint32_t bh[4], bl[4];
                uint32_t boff = (uint32_t)(ks*16*LDWE + n0w + tt*16)*2;
                ldsm_x4t(wbH + boff, bh);
                ldsm_x4t(wbL + boff, bl);
                mma16816(d[2*tt],   ah, bh);
                mma16816(d[2*tt],   al, bh);
                mma16816(d[2*tt],   ah, bl);
                mma16816(d[2*tt+1], ah, bh+2);
                mma16816(d[2*tt+1], al, bh+2);
                mma16816(d[2*tt+1], ah, bl+2);
            }
        }
        CP_WAIT0();
        __syncthreads();
    }
    bufp = (bufp + NCH) & 1;

    if (!TOGLOBAL) {
        char* HHp = smraw + hh_off;
        char* HLp = smraw + hl_off;
        #pragma unroll
        for (int t = 0; t < NT; ++t) {
            int n = n0w + t*8 + (lane & 3)*2;
            float2 bb = *(const float2*)(bias + n);
            int r = r0 + (lane >> 2);
            float v0 = d[t][0] + bb.x, v1 = d[t][1] + bb.y;
            float v2 = d[t][2] + bb.x, v3 = d[t][3] + bb.y;
            if (RELU) {
                v0 = fmaxf(v0, 0.f); v1 = fmaxf(v1, 0.f);
                v2 = fmaxf(v2, 0.f); v3 = fmaxf(v3, 0.f);
            }
            uint32_t lob, hib;
            hib = packsplit(v0, v1, lob);
            *(uint32_t*)(HHp + (r*LDX + n)*2) = hib;
            *(uint32_t*)(HLp + (r*LDX + n)*2) = lob;
            hib = packsplit(v2, v3, lob);
            *(uint32_t*)(HHp + ((r+8)*LDX + n)*2) = hib;
            *(uint32_t*)(HLp + ((r+8)*LDX + n)*2) = lob;
        }
    } else {
        const float* kc0 = g_k[k0s];
        #pragma unroll
        for (int t = 0; t < NT; ++t) {
            int n = n0w + t*8 + (lane & 3)*2;
            float2 bb = *(const float2*)(bias + n);
            #pragma unroll
            for (int hf = 0; hf < 2; ++hf) {
                int r = r0 + (lane >> 2) + hf*8;
                float v0 = d[t][2*hf]   + bb.x;
                float v1 = d[t][2*hf+1] + bb.y;
                size_t gi = (size_t)(row0 + r)*NS + n;
                *(float2*)(outG + gi) = make_float2(v0, v1);
                if (do_err) {
                    float2 k0v = *(const float2*)(kc0 + gi);
                    float2 k2v = *(const float2*)(g_k[2] + gi);
                    float2 k3v = *(const float2*)(g_k[3] + gi);
                    float2 k4v = *(const float2*)(g_k[4] + gi);
                    float2 k5v = *(const float2*)(g_k[5] + gi);
                    float2 yv  = *(const float2*)(y + gi);
                    float2 y1v = *(const float2*)(y1g + gi);
                    float e0 = dt*(c_errv[0]*k0v.x + c_errv[2]*k2v.x + c_errv[3]*k3v.x
                                 + c_errv[4]*k4v.x + c_errv[5]*k5v.x + c_errv[6]*v0);
                    float t0 = ATOLv + RTOLv*fmaxf(fabsf(yv.x), fabsf(y1v.x));
                    float r0e = e0/t0; errloc += (double)r0e*r0e;
                    float e1 = dt*(c_errv[0]*k0v.y + c_errv[2]*k2v.y + c_errv[3]*k3v.y
                                 + c_errv[4]*k4v.y + c_errv[5]*k5v.y + c_errv[6]*v1);
                    float t1 = ATOLv + RTOLv*fmaxf(fabsf(yv.y), fabsf(y1v.y));
                    float r1e = e1/t1; errloc += (double)r1e*r1e;
                }
            }
        }
    }
    __syncthreads();
}

// ---------------------------------------------------------------------------
// Full stage for one 64-row tile (round-13 structure).
// ---------------------------------------------------------------------------
__device__ void tile_stage(
    int stage, int tile, int cur, int k0s, float dt, float h0,
    const float* __restrict__ b1, const float* __restrict__ b2,
    const float* __restrict__ b3,
    char* smraw, uint32_t sm32, double& errloc,
    int& bufp, bool& w1pre)
{
    const int tid  = threadIdx.x;
    const int row0 = tile * ROWS_PB;
    const float* y = g_ybuf[cur];
    float* ynext   = g_ybuf[cur ^ 1];
    const float* kp[6] = {g_k[k0s], g_k[1], g_k[2], g_k[3], g_k[4], g_k[5]};

    float coef[6];
    int nk, outslot;
    if (stage == -1)      { nk = 0; outslot = k0s; }
    else if (stage == -2) { nk = 1; coef[0] = h0; outslot = 1; }
    else {
        nk = stage;
        #pragma unroll
        for (int j = 0; j < 6; ++j) coef[j] = dt * c_beta[stage-1][j];
        outslot = (stage < 6) ? stage : (k0s ^ 6);
    }
    float* kout = g_k[outslot];

    if (!w1pre)   // first tile-stage only: issue W1 chunk 0 under phase-0
        stage_chunk(sm32, bufp, g_w1h, g_w1l, 32*264*2, tid);

    // phase 0: build stage input, split to X (bf16 hi/lo); stage 6 -> y1
    char* XHp = smraw + XH_OFF;
    char* XLp = smraw + XL_OFF;
    for (int i = tid; i < ROWS_PB*NS/4; i += 256) {
        int r = i >> 5, c4 = i & 31, c = c4*4;
        size_t g4 = ((size_t)(row0 + r)*NS >> 2) + c4;
        float4 v = ((const float4*)y)[g4];
        for (int j = 0; j < nk; ++j) {
            float4 kv = ((const float4*)kp[j])[g4];
            v.x = fmaf(coef[j], kv.x, v.x);
            v.y = fmaf(coef[j], kv.y, v.y);
            v.z = fmaf(coef[j], kv.z, v.z);
            v.w = fmaf(coef[j], kv.w, v.w);
        }
        if (stage == 6) ((float4*)ynext)[g4] = v;
        uint32_t off = (uint32_t)(r*LDX + c)*2;
        uint32_t lob, hib;
        hib = packsplit(v.x, v.y, lob);
        *(uint32_t*)(XHp + off) = hib;
        *(uint32_t*)(XLp + off) = lob;
        hib = packsplit(v.z, v.w, lob);
        *(uint32_t*)(XHp + off + 4) = hib;
        *(uint32_t*)(XLp + off + 4) = lob;
    }
    if (!w1pre) { CP_WAIT0(); w1pre = true; }
    __syncthreads();

    double dz = 0.0;
    mma_layer<128,256,264,32,true ,false>(smraw, sm32, XH_OFF, XL_OFF,
        g_w1h, g_w1l, b1, HH_OFF, HL_OFF, nullptr, 0,
        false, 0.f, 0, nullptr, nullptr, dz,
        g_w2h, g_w2l, 32*264*2, bufp);
    mma_layer<256,256,264,32,true ,false>(smraw, sm32, HH_OFF, HL_OFF,
        g_w2h, g_w2l, b2, XH_OFF, XL_OFF, nullptr, 0,
        false, 0.f, 0, nullptr, nullptr, dz,
        g_w3h, g_w3l, 64*136*2, bufp);
    mma_layer<256,128,136,64,false,true >(smraw, sm32, XH_OFF, XL_OFF,
        g_w3h, g_w3l, b3, 0, 0, kout, row0,
        stage == 6, dt, k0s, y, ynext, errloc,
        g_w1h, g_w1l, 32*264*2, bufp);   // tail: next stage's W1 chunk 0
}

// ---------------------------------------------------------------------------
// Reductions / controller (frozen)
// ---------------------------------------------------------------------------
__device__ double block_reduce_d(double v, double* sh) {
    const int tid = threadIdx.x;
    sh[tid] = v;
    __syncthreads();
    #pragma unroll
    for (int s = 128; s > 0; s >>= 1) {
        if (tid < s) sh[tid] += sh[tid + s];
        __syncthreads();
    }
    double r = sh[0];
    __syncthreads();
    return r;
}
__device__ void ctrl_init_dev() {
    VC->sum0 = 0.0; VC->sum1 = 0.0; VC->sum2 = 0.0; VC->errsum = 0.0;
    VC->t = 0.f; VC->dt = 0.f; VC->dt_last = 0.f; VC->last_t = 0.f;
    VC->h0 = 0.f; VC->d1 = 0.f;
    VC->done = 0; VC->cur = 0; VC->k0slot = 0;
}
__device__ void ctrl_h0_dev() {
    float d0 = (float)sqrt(VC->sum0);
    float d1 = (float)sqrt(VC->sum1);
    float h0 = (d0 < 1e-5f || d1 < 1e-5f) ? 1e-6f : 0.01f * d0 / d1;
    VC->h0 = h0; VC->d1 = d1;
}
__device__ void ctrl_dt0_dev() {
    float h0 = VC->h0, d1 = VC->d1;
    float d2 = (float)sqrt(VC->sum2) / h0;
    float h1;
    if (d1 <= 1e-15f && d2 <= 1e-15f) h1 = fmaxf(1e-6f, h0 * 1e-3f);
    else h1 = powf(0.01f / fmaxf(d1, d2), 0.2f);
    VC->dt = fminf(100.f * h0, h1);
    VC->t = 0.f; VC->last_t = 0.f; VC->errsum = 0.0;
}
__device__ void ctrl_update_dev() {
    float err = (float)sqrt(VC->errsum / (double)NEL);
    float dfac = (err < 1.f) ? 1.f : 0.2f;
    float factor = fminf(10.f, fmaxf(powf(err, -0.2f) * 0.9f, dfac));
    float dtcur = VC->dt;
    float dtnew = (err == 0.f) ? dtcur * 10.f : dtcur * factor;
    dtnew = fmaxf(dtnew, 0.f);
    if (err <= 1.f) {
        VC->last_t = VC->t;
        VC->t      = VC->t + dtcur;
        VC->dt_last = dtcur;
        VC->cur    = VC->cur ^ 1;
        VC->k0slot = VC->k0slot ^ 6;
        if (VC->t >= 1.0f) VC->done = 1;
    }
    VC->dt = dtnew;
    VC->errsum = 0.0;
}

// ---------------------------------------------------------------------------
// Persistent kernel
// ---------------------------------------------------------------------------
__global__ void __launch_bounds__(256, 1)
ode_persistent(const float* __restrict__ x,
               const float* __restrict__ W1, const float* __restrict__ b1,
               const float* __restrict__ W2, const float* __restrict__ b2,
               const float* __restrict__ W3, const float* __restrict__ b3)
{
    extern __shared__ char smraw[];
    uint32_t sm32 = smem_u32(smraw);
    double* shred = (double*)smraw;
    const int tid = threadIdx.x, bid = blockIdx.x;
    int bufp = 0;
    bool w1pre = false;

    if (bid == 0 && tid == 0) ctrl_init_dev();

    build_img(g_w1h, g_w1l, W1, 128, 256, 264, bid, tid);
    build_img(g_w2h, g_w2l, W2, 256, 256, 264, bid, tid);
    build_img(g_w3h, g_w3l, W3, 256, 128, 136, bid, tid);

    for (int tile = bid; tile < NTILES; tile += NBLOCKS)
        for (int i = tid; i < ROWS_PB*NS; i += 256) {
            int r = i >> 7, cc = i & 127;
            size_t row = (size_t)tile*ROWS_PB + r;
            g_ybuf[0][row*NS + cc] = (cc < DIN) ? x[row*DIN + cc] : 0.f;
        }
    grid_barrier();

    // f0 -> slot 0
    double dummy = 0.0;
    for (int tile = bid; tile < NTILES; tile += NBLOCKS)
        tile_stage(-1, tile, 0, 0, 0.f, 0.f, b1, b2, b3, smraw, sm32, dummy,
                   bufp, w1pre);
    // d0/d1 norms
    {
        double s0 = 0.0, s1 = 0.0;
        const float4* y4 = (const float4*)g_ybuf[0];
        const float4* f4 = (const float4*)g_k[0];
        for (int tile = bid; tile < NTILES; tile += NBLOCKS) {
            size_t b4 = (size_t)tile*ROWS_PB*NS/4;
            for (int i = tid; i < ROWS_PB*NS/4; i += 256) {
                float4 y0 = y4[b4 + i], f0 = f4[b4 + i];
                float sc, a, b;
                sc = ATOLv + RTOLv*fabsf(y0.x); a = y0.x/sc; b = f0.x/sc; s0 += (double)a*a; s1 += (double)b*b;
                sc = ATOLv + RTOLv*fabsf(y0.y); a = y0.y/sc; b = f0.y/sc; s0 += (double)a*a; s1 += (double)b*b;
                sc = ATOLv + RTOLv*fabsf(y0.z); a = y0.z/sc; b = f0.z/sc; s0 += (double)a*a; s1 += (double)b*b;
                sc = ATOLv + RTOLv*fabsf(y0.w); a = y0.w/sc; b = f0.w/sc; s0 += (double)a*a; s1 += (double)b*b;
            }
        }
        double r0 = block_reduce_d(s0, shred);
        double r1 = block_reduce_d(s1, shred);
        if (tid == 0) { atomicAdd(&g_ctrl.sum0, r0); atomicAdd(&g_ctrl.sum1, r1); }
    }
    grid_barrier();
    if (bid == 0 && tid == 0) ctrl_h0_dev();
    grid_barrier();

    // probe -> slot 1
    {
        float h0v = VC->h0;
        for (int tile = bid; tile < NTILES; tile += NBLOCKS)
            tile_stage(-2, tile, 0, 0, 0.f, h0v, b1, b2, b3, smraw, sm32, dummy,
                       bufp, w1pre);
        double s2 = 0.0;
        const float4* y4 = (const float4*)g_ybuf[0];
        const float4* k04 = (const float4*)g_k[0];
        const float4* k14 = (const float4*)g_k[1];
        for (int tile = bid; tile < NTILES; tile += NBLOCKS) {
            size_t b4 = (size_t)tile*ROWS_PB*NS/4;
            for (int i = tid; i < ROWS_PB*NS/4; i += 256) {
                float4 y0 = y4[b4 + i], k0 = k04[b4 + i], k1 = k14[b4 + i];
                float sc, d;
                sc = ATOLv + RTOLv*fabsf(y0.x); d = (k1.x - k0.x)/sc; s2 += (double)d*d;
                sc = ATOLv + RTOLv*fabsf(y0.y); d = (k1.y - k0.y)/sc; s2 += (double)d*d;
                sc = ATOLv + RTOLv*fabsf(y0.z); d = (k1.z - k0.z)/sc; s2 += (double)d*d;
                sc = ATOLv + RTOLv*fabsf(y0.w); d = (k1.w - k0.w)/sc; s2 += (double)d*d;
            }
        }
        double r2 = block_reduce_d(s2, shred);
        if (tid == 0) atomicAdd(&g_ctrl.sum2, r2);
    }
    grid_barrier();
    if (bid == 0 && tid == 0) ctrl_dt0_dev();
    grid_barrier();

    // adaptive dopri5 attempts
    for (int it = 0; it < MAXIT; ++it) {
        if (VC->done) break;
        float dt = VC->dt;
        int cur = VC->cur, k0s = VC->k0slot;
        double eloc = 0.0;
        for (int tile = bid; tile < NTILES; tile += NBLOCKS)
            #pragma unroll 1
            for (int s = 1; s <= 6; ++s)
                tile_stage(s, tile, cur, k0s, dt, 0.f, b1, b2, b3,
                           smraw, sm32, eloc, bufp, w1pre);
        double rsum = block_reduce_d(eloc, shred);
        if (tid == 0) atomicAdd(&g_ctrl.errsum, rsum);
        grid_barrier();
        if (bid == 0 && tid == 0) ctrl_update_dev();
        grid_barrier();
    }
}

// ---------------------------------------------------------------------------
// Final: 4th-order interpolation at t=1, then linear layer @ Wl + bl
// ---------------------------------------------------------------------------
__global__ void __launch_bounds__(256)
final_kernel(const float* __restrict__ Wl, const float* __restrict__ bl,
             float* __restrict__ out)
{
    __shared__ float yt_s[64*132];
    __shared__ float wl_s[128*NOUTC];
    __shared__ float bl_s[NOUTC];
    const int tid = threadIdx.x;
    const int row0 = blockIdx.x * 64;

    for (int i = tid; i < 128*NOUTC; i += 256) wl_s[i] = Wl[i];
    if (tid < NOUTC) bl_s[tid] = bl[tid];

    const int cur = g_ctrl.cur;
    const int k0s = g_ctrl.k0slot;
    const float dtl = g_ctrl.dt_last;
    const float s  = (1.0f - g_ctrl.last_t) / (g_ctrl.t - g_ctrl.last_t);
    const float* yprev = g_ybuf[cur ^ 1];
    const float* ycur  = g_ybuf[cur];
    const float* k0p = g_k[k0s ^ 6];
    const float* k6p = g_k[k0s];

    for (int i = tid; i < 64*NS; i += 256) {
        int r = i >> 7, cc = i & 127;
        size_t g = (size_t)(row0 + r)*NS + cc;
        float y0e = yprev[g], y1e = ycur[g];
        float k0v = k0p[g], k6v = k6p[g];
        float kmid = c_midv[0]*k0v + c_midv[2]*g_k[2][g] + c_midv[3]*g_k[3][g]
                   + c_midv[4]*g_k[4][g] + c_midv[5]*g_k[5][g] + c_midv[6]*k6v;
        float ymid = y0e + dtl * kmid;
        float dy0 = dtl * k0v, dy1 = dtl * k6v;
        float a = -2.f*dy0 + 2.f*dy1 -  8.f*y0e -  8.f*y1e + 16.f*ymid;
        float b =  5.f*dy0 - 3.f*dy1 + 18.f*y0e + 14.f*y1e - 32.f*ymid;
        float c = -4.f*dy0 +     dy1 - 11.f*y0e -  5.f*y1e + 16.f*ymid;
        float d = dy0, e = y0e;
        yt_s[r*132 + cc] = (((a*s + b)*s + c)*s + d)*s + e;
    }
    __syncthreads();

    for (int idx = tid; idx < 64*NOUTC; idx += 256) {
        int r = idx / NOUTC, c = idx % NOUTC;
        float acc = bl_s[c];
        const float* yr = yt_s + r*132;
        #pragma unroll 8
        for (int kk = 0; kk < NS; ++kk)
            acc = fmaf(yr[kk], wl_s[kk*NOUTC + c], acc);
        out[(size_t)(row0 + r)*NOUTC + c] = acc;
    }
}

extern "C" void kernel_launch(void* const* d_in, const int* in_sizes, int n_in,
                              void* d_out, int out_size)
{
    const float* x  = (const float*)d_in[0];
    const float* W1 = (const float*)d_in[1];
    const float* b1 = (const float*)d_in[2];
    const float* W2 = (const float*)d_in[3];
    const float* b2 = (const float*)d_in[4];
    const float* W3 = (const float*)d_in[5];
    const float* b3 = (const float*)d_in[6];
    const float* Wl = (const float*)d_in[7];
    const float* bl = (const float*)d_in[8];
    float* out = (float*)d_out;

    cudaFuncSetAttribute(ode_persistent,
                         cudaFuncAttributeMaxDynamicSharedMemorySize, SMEM_BYTES);
    ode_persistent<<<NBLOCKS, 256, SMEM_BYTES>>>(x, W1, b1, W2, b2, W3, b3);
    final_kernel<<<NTILES, 256>>>(Wl, bl, out);
}